// round 6
// baseline (speedup 1.0000x reference)
#include <cuda_runtime.h>
#include <math_constants.h>

#define DMODEL 1024
#define NHEADS 16
#define HDIM   64
#define BATCH  4
#define SEQ    2048
#define ROWS   (BATCH*SEQ)   // 8192

// ---- scratch (static device globals; no runtime allocation) ----
__device__ float g_Qp[(size_t)ROWS*DMODEL];
__device__ float g_Kp[(size_t)ROWS*DMODEL];
__device__ float g_Vp[(size_t)ROWS*DMODEL];
__device__ float g_Z [(size_t)ROWS*DMODEL];

// ============================================================================
// SGEMM with bias: C[M,N] = A[M,K] @ B[K,N] + bias[N], all row-major.
// BM=BN=128, BK=8, 256 threads, 8x8 per-thread tile, float4 IO.
// Requires M%128==0, N%128==0, K%8==0.
// ============================================================================
__global__ __launch_bounds__(256, 2)
void sgemm_bias(const float* __restrict__ A, const float* __restrict__ B,
                const float* __restrict__ bias, float* __restrict__ C,
                int M, int N, int K)
{
    const int BM = 128, BN = 128, BK = 8;
    __shared__ float As[BK][BM];   // transposed A tile
    __shared__ float Bs[BK][BN];

    const int tid  = threadIdx.x;
    const int tcol = tid & 15;     // 16 col-groups of 8
    const int trow = tid >> 4;     // 16 row-groups of 8
    const int aRow = tid >> 1;           // 0..127
    const int aCol = (tid & 1) << 2;     // 0 or 4
    const int bRow = tid >> 5;           // 0..7
    const int bCol = (tid & 31) << 2;    // 0..124

    const float* Ab = A + (size_t)blockIdx.y * BM * K;
    const float* Bb = B + (size_t)blockIdx.x * BN;

    float acc[8][8];
    #pragma unroll
    for (int i = 0; i < 8; i++)
        #pragma unroll
        for (int j = 0; j < 8; j++) acc[i][j] = 0.f;

    for (int k0 = 0; k0 < K; k0 += BK) {
        float4 a4 = *(const float4*)(Ab + (size_t)aRow * K + k0 + aCol);
        As[aCol + 0][aRow] = a4.x;
        As[aCol + 1][aRow] = a4.y;
        As[aCol + 2][aRow] = a4.z;
        As[aCol + 3][aRow] = a4.w;
        *(float4*)(&Bs[bRow][bCol]) =
            *(const float4*)(Bb + (size_t)(k0 + bRow) * N + bCol);
        __syncthreads();

        #pragma unroll
        for (int kk = 0; kk < BK; kk++) {
            float af[8], bf[8];
            *(float4*)(af)     = *(const float4*)(&As[kk][trow * 8]);
            *(float4*)(af + 4) = *(const float4*)(&As[kk][trow * 8 + 4]);
            *(float4*)(bf)     = *(const float4*)(&Bs[kk][tcol * 8]);
            *(float4*)(bf + 4) = *(const float4*)(&Bs[kk][tcol * 8 + 4]);
            #pragma unroll
            for (int i = 0; i < 8; i++)
                #pragma unroll
                for (int j = 0; j < 8; j++)
                    acc[i][j] = fmaf(af[i], bf[j], acc[i][j]);
        }
        __syncthreads();
    }

    const int row0 = blockIdx.y * BM + trow * 8;
    const int col0 = blockIdx.x * BN + tcol * 8;
    #pragma unroll
    for (int i = 0; i < 8; i++) {
        #pragma unroll
        for (int j = 0; j < 8; j += 4) {
            float4 v;
            v.x = acc[i][j + 0] + bias[col0 + j + 0];
            v.y = acc[i][j + 1] + bias[col0 + j + 1];
            v.z = acc[i][j + 2] + bias[col0 + j + 2];
            v.w = acc[i][j + 3] + bias[col0 + j + 3];
            *(float4*)(C + (size_t)(row0 + i) * N + col0 + j) = v;
        }
    }
}

// ============================================================================
// Fused flash attention, fp32.
// Block: 128 q-rows of one (b,h); loops over Sk in tiles of 64.
// 256 threads: tcol = tid&15 (owns 4 strided cols c=tcol+16j), trow = tid>>4
// (owns 8 q-rows r=trow*8+i). Online softmax via shfl over the 16-lane group.
// Stride-66 smem rows -> conflict-free scalar fragment reads.
// ============================================================================
#define BQ   128
#define BKV  64
#define SSTR 66
#define ATTN_SMEM ((BQ*SSTR + BKV*SSTR + BKV*HDIM + BQ*SSTR) * sizeof(float))

__global__ __launch_bounds__(256, 2)
void attn_kernel()
{
    extern __shared__ float sm[];
    float* sQ = sm;                     // [BQ][SSTR]   (pre-scaled by 1/sqrt(d))
    float* sK = sQ + BQ * SSTR;         // [BKV][SSTR]
    float* sV = sK + BKV * SSTR;        // [BKV][HDIM]
    float* sP = sV + BKV * HDIM;        // [BQ][SSTR]

    const int tid  = threadIdx.x;
    const int tcol = tid & 15;
    const int trow = tid >> 4;
    const int b = blockIdx.y >> 4;
    const int h = blockIdx.y & 15;
    const size_t qrow0 = (size_t)b * SEQ + (size_t)blockIdx.x * BQ;

    const float* Qg = g_Qp + qrow0 * DMODEL + h * HDIM;
    const float* Kg = g_Kp + (size_t)b * SEQ * DMODEL + h * HDIM;
    const float* Vg = g_Vp + (size_t)b * SEQ * DMODEL + h * HDIM;

    // ---- load Q tile once (scale folded in) ----
    #pragma unroll
    for (int it = 0; it < (BQ * HDIM / 4) / 256; ++it) {   // 8 iters
        int f = tid + it * 256;
        int r = f >> 4;
        int c = (f & 15) << 2;
        float4 v = *(const float4*)(Qg + (size_t)r * DMODEL + c);
        sQ[r * SSTR + c + 0] = v.x * 0.125f;
        sQ[r * SSTR + c + 1] = v.y * 0.125f;
        sQ[r * SSTR + c + 2] = v.z * 0.125f;
        sQ[r * SSTR + c + 3] = v.w * 0.125f;
    }

    float o[8][4], m[8], l[8];
    #pragma unroll
    for (int i = 0; i < 8; i++) {
        m[i] = -CUDART_INF_F; l[i] = 0.f;
        #pragma unroll
        for (int j = 0; j < 4; j++) o[i][j] = 0.f;
    }

    for (int kb = 0; kb < SEQ; kb += BKV) {
        __syncthreads();   // prev PV done before overwriting K/V/P
        // ---- load K,V tiles ----
        #pragma unroll
        for (int it = 0; it < (BKV * HDIM / 4) / 256; ++it) {  // 4 iters
            int f = tid + it * 256;
            int r = f >> 4;
            int c = (f & 15) << 2;
            float4 kv = *(const float4*)(Kg + (size_t)(kb + r) * DMODEL + c);
            sK[r * SSTR + c + 0] = kv.x;
            sK[r * SSTR + c + 1] = kv.y;
            sK[r * SSTR + c + 2] = kv.z;
            sK[r * SSTR + c + 3] = kv.w;
            float4 vv = *(const float4*)(Vg + (size_t)(kb + r) * DMODEL + c);
            *(float4*)(sV + r * HDIM + c) = vv;
        }
        __syncthreads();

        // ---- S = Q @ K^T  (8x4 per thread) ----
        float s[8][4];
        #pragma unroll
        for (int i = 0; i < 8; i++)
            #pragma unroll
            for (int j = 0; j < 4; j++) s[i][j] = 0.f;

        const float* qb  = sQ + trow * 8 * SSTR;
        const float* kb0 = sK + tcol * SSTR;
        #pragma unroll 4
        for (int kk = 0; kk < HDIM; kk++) {
            float qf[8], kf[4];
            #pragma unroll
            for (int i = 0; i < 8; i++) qf[i] = qb[i * SSTR + kk];
            #pragma unroll
            for (int j = 0; j < 4; j++) kf[j] = kb0[j * 16 * SSTR + kk];
            #pragma unroll
            for (int i = 0; i < 8; i++)
                #pragma unroll
                for (int j = 0; j < 4; j++)
                    s[i][j] = fmaf(qf[i], kf[j], s[i][j]);
        }

        // ---- online softmax (row reduce across the 16-lane tcol group) ----
        #pragma unroll
        for (int i = 0; i < 8; i++) {
            float mt = fmaxf(fmaxf(s[i][0], s[i][1]), fmaxf(s[i][2], s[i][3]));
            #pragma unroll
            for (int off = 1; off < 16; off <<= 1)
                mt = fmaxf(mt, __shfl_xor_sync(0xffffffffu, mt, off));
            float mn   = fmaxf(m[i], mt);
            float corr = __expf(m[i] - mn);
            m[i] = mn;
            float rs = 0.f;
            #pragma unroll
            for (int j = 0; j < 4; j++) {
                float p = __expf(s[i][j] - mn);
                s[i][j] = p;
                rs += p;
            }
            #pragma unroll
            for (int off = 1; off < 16; off <<= 1)
                rs += __shfl_xor_sync(0xffffffffu, rs, off);
            l[i] = l[i] * corr + rs;
            #pragma unroll
            for (int j = 0; j < 4; j++) o[i][j] *= corr;
            #pragma unroll
            for (int j = 0; j < 4; j++)
                sP[(trow * 8 + i) * SSTR + tcol + 16 * j] = s[i][j];
        }
        __syncthreads();

        // ---- O += P @ V ----
        const float* pb = sP + trow * 8 * SSTR;
        #pragma unroll 4
        for (int kk = 0; kk < BKV; kk++) {
            float pf[8], vf[4];
            #pragma unroll
            for (int i = 0; i < 8; i++) pf[i] = pb[i * SSTR + kk];
            #pragma unroll
            for (int j = 0; j < 4; j++) vf[j] = sV[kk * HDIM + tcol + 16 * j];
            #pragma unroll
            for (int i = 0; i < 8; i++)
                #pragma unroll
                for (int j = 0; j < 4; j++)
                    o[i][j] = fmaf(pf[i], vf[j], o[i][j]);
        }
    }

    // ---- normalize + write Z in [B*S, H*d] layout ----
    #pragma unroll
    for (int i = 0; i < 8; i++) {
        float inv = 1.f / l[i];
        float* zr = g_Z + (qrow0 + trow * 8 + i) * DMODEL + h * HDIM + tcol;
        #pragma unroll
        for (int j = 0; j < 4; j++)
            zr[16 * j] = o[i][j] * inv;
    }
}

// ============================================================================
// Launch: 3 projections -> attention -> output projection.
// ============================================================================
extern "C" void kernel_launch(void* const* d_in, const int* in_sizes, int n_in,
                              void* d_out, int out_size)
{
    const float* query = (const float*)d_in[0];
    const float* key   = (const float*)d_in[1];
    const float* value = (const float*)d_in[2];
    const float* Wq    = (const float*)d_in[3];
    const float* bq    = (const float*)d_in[4];
    const float* Wk    = (const float*)d_in[5];
    const float* bk    = (const float*)d_in[6];
    const float* Wv    = (const float*)d_in[7];
    const float* bv    = (const float*)d_in[8];
    const float* Wo    = (const float*)d_in[9];
    const float* bo    = (const float*)d_in[10];

    float *Qp, *Kp, *Vp, *Zp;
    cudaGetSymbolAddress((void**)&Qp, g_Qp);
    cudaGetSymbolAddress((void**)&Kp, g_Kp);
    cudaGetSymbolAddress((void**)&Vp, g_Vp);
    cudaGetSymbolAddress((void**)&Zp, g_Z);

    dim3 gg(DMODEL / 128, ROWS / 128);
    sgemm_bias<<<gg, 256>>>(query, Wq, bq, Qp, ROWS, DMODEL, DMODEL);
    sgemm_bias<<<gg, 256>>>(key,   Wk, bk, Kp, ROWS, DMODEL, DMODEL);
    sgemm_bias<<<gg, 256>>>(value, Wv, bv, Vp, ROWS, DMODEL, DMODEL);

    cudaFuncSetAttribute(attn_kernel, cudaFuncAttributeMaxDynamicSharedMemorySize,
                         (int)ATTN_SMEM);
    attn_kernel<<<dim3(SEQ / BQ, BATCH * NHEADS), 256, ATTN_SMEM>>>();

    sgemm_bias<<<gg, 256>>>(Zp, Wo, bo, (float*)d_out, ROWS, DMODEL, DMODEL);
}

// round 8
// speedup vs baseline: 2.8375x; 2.8375x over previous
#include <cuda_runtime.h>
#include <math_constants.h>

#define DMODEL 1024
#define NHEADS 16
#define HDIM   64
#define BATCH  4
#define SEQ    2048
#define ROWS   (BATCH*SEQ)   // 8192

// ---- scratch (static device globals; no runtime allocation) ----
__device__ float g_Qp[(size_t)ROWS*DMODEL];
__device__ float g_Kp[(size_t)ROWS*DMODEL];
__device__ float g_Vp[(size_t)ROWS*DMODEL];
__device__ float g_Z [(size_t)ROWS*DMODEL];

// ---- tf32 helpers ----
__device__ __forceinline__ unsigned f2tf(float x) {
    unsigned r;
    asm("cvt.rna.tf32.f32 %0, %1;" : "=r"(r) : "f"(x));
    return r;
}

// D += A@B for m16n8k8 tf32. d: 4 floats, a: 4 tf32 regs, b: 2 tf32 regs.
// Fragment layout (g = lane>>2, tg = lane&3):
//   a0:(g,tg) a1:(g+8,tg) a2:(g,tg+4) a3:(g+8,tg+4)
//   b0:(k=tg,n=g) b1:(k=tg+4,n=g)
//   c0:(g,2tg) c1:(g,2tg+1) c2:(g+8,2tg) c3:(g+8,2tg+1)
__device__ __forceinline__ void mma8(float* d, const unsigned* a, const unsigned* b) {
    asm volatile(
        "mma.sync.aligned.m16n8k8.row.col.f32.tf32.tf32.f32 "
        "{%0,%1,%2,%3}, {%4,%5,%6,%7}, {%8,%9}, {%0,%1,%2,%3};\n"
        : "+f"(d[0]), "+f"(d[1]), "+f"(d[2]), "+f"(d[3])
        : "r"(a[0]), "r"(a[1]), "r"(a[2]), "r"(a[3]), "r"(b[0]), "r"(b[1]));
}

// ============================================================================
// TF32 tensor-core GEMM with bias: C[M,N] = A[M,K] @ B[K,N] + bias[N].
// Block tile 128x128, BK=16, 256 threads (8 warps, 2x4), warp tile 64x32.
// smem strides: As 20 (banks (20g+tg)%32 all distinct), Bs 136 ((8tg+g)%32 distinct).
// ============================================================================
__global__ __launch_bounds__(256)
void gemm_tf32(const float* __restrict__ A, const float* __restrict__ B,
               const float* __restrict__ bias, float* __restrict__ C,
               int M, int N, int K)
{
    __shared__ unsigned As[128 * 20];
    __shared__ unsigned Bs[16 * 136];

    const int tid  = threadIdx.x;
    const int warp = tid >> 5, lane = tid & 31;
    const int g = lane >> 2, tg = lane & 3;
    const int wm = (warp >> 2) * 64;   // warp m-origin in tile
    const int wn = (warp & 3)  * 32;   // warp n-origin in tile

    const float* Ab = A + (size_t)blockIdx.y * 128 * K;
    const float* Bb = B + blockIdx.x * 128;

    float acc[4][4][4];
    #pragma unroll
    for (int mi = 0; mi < 4; mi++)
        #pragma unroll
        for (int ni = 0; ni < 4; ni++)
            #pragma unroll
            for (int r = 0; r < 4; r++) acc[mi][ni][r] = 0.f;

    for (int k0 = 0; k0 < K; k0 += 16) {
        // A tile 128x16 -> As[m][k], tf32-converted
        #pragma unroll
        for (int it = 0; it < 2; ++it) {
            int idx = tid + it * 256;
            int r = idx >> 2, c = (idx & 3) * 4;
            float4 v = *(const float4*)(Ab + (size_t)r * K + k0 + c);
            unsigned* d = &As[r * 20 + c];
            d[0] = f2tf(v.x); d[1] = f2tf(v.y); d[2] = f2tf(v.z); d[3] = f2tf(v.w);
        }
        // B tile 16x128 -> Bs[k][n]
        #pragma unroll
        for (int it = 0; it < 2; ++it) {
            int idx = tid + it * 256;
            int r = idx >> 5, c = (idx & 31) * 4;
            float4 v = *(const float4*)(Bb + (size_t)(k0 + r) * N + c);
            unsigned* d = &Bs[r * 136 + c];
            d[0] = f2tf(v.x); d[1] = f2tf(v.y); d[2] = f2tf(v.z); d[3] = f2tf(v.w);
        }
        __syncthreads();

        #pragma unroll
        for (int ks = 0; ks < 2; ++ks) {
            const int kk = ks * 8;
            unsigned a[4][4], b[4][2];
            #pragma unroll
            for (int mi = 0; mi < 4; ++mi) {
                int m = wm + mi * 16;
                a[mi][0] = As[(m + g    ) * 20 + kk + tg];
                a[mi][1] = As[(m + g + 8) * 20 + kk + tg];
                a[mi][2] = As[(m + g    ) * 20 + kk + tg + 4];
                a[mi][3] = As[(m + g + 8) * 20 + kk + tg + 4];
            }
            #pragma unroll
            for (int ni = 0; ni < 4; ++ni) {
                int n = wn + ni * 8;
                b[ni][0] = Bs[(kk + tg    ) * 136 + n + g];
                b[ni][1] = Bs[(kk + tg + 4) * 136 + n + g];
            }
            #pragma unroll
            for (int mi = 0; mi < 4; ++mi)
                #pragma unroll
                for (int ni = 0; ni < 4; ++ni)
                    mma8(acc[mi][ni], a[mi], b[ni]);
        }
        __syncthreads();
    }

    // epilogue: bias + store (float2 per row-half)
    #pragma unroll
    for (int mi = 0; mi < 4; ++mi) {
        #pragma unroll
        for (int ni = 0; ni < 4; ++ni) {
            int row = blockIdx.y * 128 + wm + mi * 16 + g;
            int col = blockIdx.x * 128 + wn + ni * 8 + 2 * tg;
            float b0 = bias[col], b1 = bias[col + 1];
            float2 v0 = make_float2(acc[mi][ni][0] + b0, acc[mi][ni][1] + b1);
            float2 v1 = make_float2(acc[mi][ni][2] + b0, acc[mi][ni][3] + b1);
            *(float2*)(C + (size_t)row * N + col)       = v0;
            *(float2*)(C + (size_t)(row + 8) * N + col) = v1;
        }
    }
}

// ============================================================================
// Fused flash attention, tf32 tensor cores.
// Block: 128 q-rows of one (b,h); 8 warps x 16 rows each; kv tiles of 64.
// smem (dynamic, tf32 bits): sQ[128][68], sK[64][68], sV[64][72], sP[128][68].
// All fragment LDS patterns verified 32-bank conflict-free:
//   sQ/sP a-frag: (4g+tg)%32 distinct; sK b-frag: (4g+tg); sV b-frag: (8tg+g).
// sP rows are per-warp private -> only __syncwarp between P write and PV read.
// ============================================================================
#define BQ   128
#define BKV  64
#define SQ_STR 68
#define SK_STR 68
#define SV_STR 72
#define SP_STR 68
#define OFF_K  (BQ * SQ_STR)
#define OFF_V  (OFF_K + BKV * SK_STR)
#define OFF_P  (OFF_V + BKV * SV_STR)
#define ATTN_SMEM ((OFF_P + BQ * SP_STR) * sizeof(unsigned))

__global__ __launch_bounds__(256)
void attn_tc_kernel()
{
    extern __shared__ unsigned sm[];
    unsigned* sQ = sm;
    unsigned* sK = sm + OFF_K;
    unsigned* sV = sm + OFF_V;
    unsigned* sP = sm + OFF_P;

    const int tid  = threadIdx.x;
    const int warp = tid >> 5, lane = tid & 31;
    const int g = lane >> 2, tg = lane & 3;
    const int wr0 = warp * 16;              // warp's q-row origin in tile
    const int b = blockIdx.y >> 4;
    const int h = blockIdx.y & 15;
    const size_t qrow0 = (size_t)b * SEQ + (size_t)blockIdx.x * BQ;

    const float* Qg = g_Qp + qrow0 * DMODEL + h * HDIM;
    const float* Kg = g_Kp + (size_t)b * SEQ * DMODEL + h * HDIM;
    const float* Vg = g_Vp + (size_t)b * SEQ * DMODEL + h * HDIM;

    // ---- load Q tile once (scale 1/8 folded in, tf32) ----
    #pragma unroll
    for (int it = 0; it < 8; ++it) {          // 2048 float4 / 256 thr
        int idx = tid + it * 256;
        int r = idx >> 4, c = (idx & 15) * 4;
        float4 v = *(const float4*)(Qg + (size_t)r * DMODEL + c);
        unsigned* d = &sQ[r * SQ_STR + c];
        d[0] = f2tf(v.x * 0.125f); d[1] = f2tf(v.y * 0.125f);
        d[2] = f2tf(v.z * 0.125f); d[3] = f2tf(v.w * 0.125f);
    }

    float o[8][4];
    #pragma unroll
    for (int ni = 0; ni < 8; ni++)
        #pragma unroll
        for (int r = 0; r < 4; r++) o[ni][r] = 0.f;
    float m0 = -CUDART_INF_F, m1 = -CUDART_INF_F, l0 = 0.f, l1 = 0.f;

    for (int kb = 0; kb < SEQ; kb += BKV) {
        __syncthreads();   // prior PV reads of sK/sV done in all warps
        // ---- load K,V tiles (64x64 each), tf32 ----
        #pragma unroll
        for (int it = 0; it < 4; ++it) {      // 1024 float4 each
            int idx = tid + it * 256;
            int r = idx >> 4, c = (idx & 15) * 4;
            float4 kv = *(const float4*)(Kg + (size_t)(kb + r) * DMODEL + c);
            unsigned* dk = &sK[r * SK_STR + c];
            dk[0] = f2tf(kv.x); dk[1] = f2tf(kv.y); dk[2] = f2tf(kv.z); dk[3] = f2tf(kv.w);
            float4 vv = *(const float4*)(Vg + (size_t)(kb + r) * DMODEL + c);
            unsigned* dv = &sV[r * SV_STR + c];
            dv[0] = f2tf(vv.x); dv[1] = f2tf(vv.y); dv[2] = f2tf(vv.z); dv[3] = f2tf(vv.w);
        }
        __syncthreads();

        // ---- S = Q @ K^T : warp computes 16 x 64 ----
        float s[8][4];
        #pragma unroll
        for (int ni = 0; ni < 8; ni++)
            #pragma unroll
            for (int r = 0; r < 4; r++) s[ni][r] = 0.f;

        #pragma unroll
        for (int ks = 0; ks < 8; ++ks) {
            const int kk = ks * 8;
            unsigned a[4];
            a[0] = sQ[(wr0 + g    ) * SQ_STR + kk + tg];
            a[1] = sQ[(wr0 + g + 8) * SQ_STR + kk + tg];
            a[2] = sQ[(wr0 + g    ) * SQ_STR + kk + tg + 4];
            a[3] = sQ[(wr0 + g + 8) * SQ_STR + kk + tg + 4];
            #pragma unroll
            for (int ni = 0; ni < 8; ++ni) {
                unsigned bfr[2];
                bfr[0] = sK[(ni * 8 + g) * SK_STR + kk + tg];
                bfr[1] = sK[(ni * 8 + g) * SK_STR + kk + tg + 4];
                mma8(s[ni], a, bfr);
            }
        }

        // ---- online softmax. Thread owns rows (wr0+g) [c0,c1] and (wr0+g+8) [c2,c3]. ----
        float mx0 = -CUDART_INF_F, mx1 = -CUDART_INF_F;
        #pragma unroll
        for (int ni = 0; ni < 8; ++ni) {
            mx0 = fmaxf(mx0, fmaxf(s[ni][0], s[ni][1]));
            mx1 = fmaxf(mx1, fmaxf(s[ni][2], s[ni][3]));
        }
        mx0 = fmaxf(mx0, __shfl_xor_sync(0xffffffffu, mx0, 1));
        mx0 = fmaxf(mx0, __shfl_xor_sync(0xffffffffu, mx0, 2));
        mx1 = fmaxf(mx1, __shfl_xor_sync(0xffffffffu, mx1, 1));
        mx1 = fmaxf(mx1, __shfl_xor_sync(0xffffffffu, mx1, 2));

        float mn0 = fmaxf(m0, mx0), mn1 = fmaxf(m1, mx1);
        float corr0 = __expf(m0 - mn0), corr1 = __expf(m1 - mn1);
        m0 = mn0; m1 = mn1;

        float sum0 = 0.f, sum1 = 0.f;
        #pragma unroll
        for (int ni = 0; ni < 8; ++ni) {
            float p0 = __expf(s[ni][0] - mn0);
            float p1 = __expf(s[ni][1] - mn0);
            float p2 = __expf(s[ni][2] - mn1);
            float p3 = __expf(s[ni][3] - mn1);
            sum0 += p0 + p1; sum1 += p2 + p3;
            int col = ni * 8 + 2 * tg;
            sP[(wr0 + g    ) * SP_STR + col    ] = f2tf(p0);
            sP[(wr0 + g    ) * SP_STR + col + 1] = f2tf(p1);
            sP[(wr0 + g + 8) * SP_STR + col    ] = f2tf(p2);
            sP[(wr0 + g + 8) * SP_STR + col + 1] = f2tf(p3);
        }
        sum0 += __shfl_xor_sync(0xffffffffu, sum0, 1);
        sum0 += __shfl_xor_sync(0xffffffffu, sum0, 2);
        sum1 += __shfl_xor_sync(0xffffffffu, sum1, 1);
        sum1 += __shfl_xor_sync(0xffffffffu, sum1, 2);
        l0 = l0 * corr0 + sum0;
        l1 = l1 * corr1 + sum1;
        #pragma unroll
        for (int ni = 0; ni < 8; ++ni) {
            o[ni][0] *= corr0; o[ni][1] *= corr0;
            o[ni][2] *= corr1; o[ni][3] *= corr1;
        }
        __syncwarp();   // sP rows are warp-private; cross-lane visibility only

        // ---- O += P @ V ----
        #pragma unroll
        for (int ks = 0; ks < 8; ++ks) {
            const int kk = ks * 8;
            unsigned a[4];
            a[0] = sP[(wr0 + g    ) * SP_STR + kk + tg];
            a[1] = sP[(wr0 + g + 8) * SP_STR + kk + tg];
            a[2] = sP[(wr0 + g    ) * SP_STR + kk + tg + 4];
            a[3] = sP[(wr0 + g + 8) * SP_STR + kk + tg + 4];
            #pragma unroll
            for (int ni = 0; ni < 8; ++ni) {
                unsigned bfr[2];
                bfr[0] = sV[(kk + tg    ) * SV_STR + ni * 8 + g];
                bfr[1] = sV[(kk + tg + 4) * SV_STR + ni * 8 + g];
                mma8(o[ni], a, bfr);
            }
        }
    }

    // ---- normalize + write Z in [B*S, H*d] layout ----
    float inv0 = 1.f / l0, inv1 = 1.f / l1;
    #pragma unroll
    for (int ni = 0; ni < 8; ++ni) {
        int col = h * HDIM + ni * 8 + 2 * tg;
        size_t r0 = qrow0 + wr0 + g;
        *(float2*)(g_Z + r0 * DMODEL + col) =
            make_float2(o[ni][0] * inv0, o[ni][1] * inv0);
        *(float2*)(g_Z + (r0 + 8) * DMODEL + col) =
            make_float2(o[ni][2] * inv1, o[ni][3] * inv1);
    }
}

// ============================================================================
// Launch: 3 projections -> attention -> output projection.
// ============================================================================
extern "C" void kernel_launch(void* const* d_in, const int* in_sizes, int n_in,
                              void* d_out, int out_size)
{
    const float* query = (const float*)d_in[0];
    const float* key   = (const float*)d_in[1];
    const float* value = (const float*)d_in[2];
    const float* Wq    = (const float*)d_in[3];
    const float* bq    = (const float*)d_in[4];
    const float* Wk    = (const float*)d_in[5];
    const float* bk    = (const float*)d_in[6];
    const float* Wv    = (const float*)d_in[7];
    const float* bv    = (const float*)d_in[8];
    const float* Wo    = (const float*)d_in[9];
    const float* bo    = (const float*)d_in[10];

    float *Qp, *Kp, *Vp, *Zp;
    cudaGetSymbolAddress((void**)&Qp, g_Qp);
    cudaGetSymbolAddress((void**)&Kp, g_Kp);
    cudaGetSymbolAddress((void**)&Vp, g_Vp);
    cudaGetSymbolAddress((void**)&Zp, g_Z);

    dim3 gg(DMODEL / 128, ROWS / 128);
    gemm_tf32<<<gg, 256>>>(query, Wq, bq, Qp, ROWS, DMODEL, DMODEL);
    gemm_tf32<<<gg, 256>>>(key,   Wk, bk, Kp, ROWS, DMODEL, DMODEL);
    gemm_tf32<<<gg, 256>>>(value, Wv, bv, Vp, ROWS, DMODEL, DMODEL);

    cudaFuncSetAttribute(attn_tc_kernel, cudaFuncAttributeMaxDynamicSharedMemorySize,
                         (int)ATTN_SMEM);
    attn_tc_kernel<<<dim3(SEQ / BQ, BATCH * NHEADS), 256, ATTN_SMEM>>>();

    gemm_tf32<<<gg, 256>>>(Zp, Wo, bo, (float*)d_out, ROWS, DMODEL, DMODEL);
}

// round 11
// speedup vs baseline: 3.1455x; 1.1085x over previous
#include <cuda_runtime.h>
#include <math_constants.h>

#define DMODEL 1024
#define NHEADS 16
#define HDIM   64
#define BATCH  4
#define SEQ    2048
#define ROWS   (BATCH*SEQ)   // 8192

// ---- scratch (static device globals; no runtime allocation) ----
__device__ float g_Qp[(size_t)ROWS*DMODEL];
__device__ float g_Kp[(size_t)ROWS*DMODEL];
__device__ float g_Vp[(size_t)ROWS*DMODEL];
__device__ float g_Z [(size_t)ROWS*DMODEL];

// ---- tf32 helpers ----
__device__ __forceinline__ unsigned f2tf(float x) {
    unsigned r;
    asm("cvt.rna.tf32.f32 %0, %1;" : "=r"(r) : "f"(x));
    return r;
}

// D += A@B for m16n8k8 tf32 (g=lane>>2, tg=lane&3):
//   a0:(g,tg) a1:(g+8,tg) a2:(g,tg+4) a3:(g+8,tg+4)
//   b0:(k=tg,n=g) b1:(k=tg+4,n=g)
//   c0:(g,2tg) c1:(g,2tg+1) c2:(g+8,2tg) c3:(g+8,2tg+1)
__device__ __forceinline__ void mma8(float* d, const unsigned* a, const unsigned* b) {
    asm volatile(
        "mma.sync.aligned.m16n8k8.row.col.f32.tf32.tf32.f32 "
        "{%0,%1,%2,%3}, {%4,%5,%6,%7}, {%8,%9}, {%0,%1,%2,%3};\n"
        : "+f"(d[0]), "+f"(d[1]), "+f"(d[2]), "+f"(d[3])
        : "r"(a[0]), "r"(a[1]), "r"(a[2]), "r"(a[3]), "r"(b[0]), "r"(b[1]));
}

// ldmatrix x4: 4 8x8 b16 tiles == 4 8x4 tf32 tiles. addr = shared-space BYTE addr.
__device__ __forceinline__ void ldsm4(unsigned& r0, unsigned& r1, unsigned& r2,
                                      unsigned& r3, unsigned addr) {
    asm volatile("ldmatrix.sync.aligned.m8n8.x4.shared.b16 {%0,%1,%2,%3}, [%4];\n"
        : "=r"(r0), "=r"(r1), "=r"(r2), "=r"(r3) : "r"(addr));
}

// ============================================================================
// Merged TF32 GEMM with bias: C[z] = A[z] @ W[z] + bias[z]; z = blockIdx.z.
// 128x128 tile, BK=16, 256 thr (8 warps 2x4, warp 64x32), double-buffered smem,
// register-staged global prefetch, ldmatrix A-frags, scalar-LDS B-frags.
// As stride 20 (LDSM segs 5r mod 8 distinct); Bs stride 136 (8tg+g distinct).
// ============================================================================
#define ASTR 20
#define BSTR 136

__global__ __launch_bounds__(256, 2)
void gemm3_tf32(const float* __restrict__ A0, const float* __restrict__ A1,
                const float* __restrict__ A2,
                const float* __restrict__ W0, const float* __restrict__ W1,
                const float* __restrict__ W2,
                const float* __restrict__ bb0, const float* __restrict__ bb1,
                const float* __restrict__ bb2,
                float* __restrict__ C0, float* __restrict__ C1,
                float* __restrict__ C2)
{
    __shared__ unsigned As[2][128 * ASTR];
    __shared__ unsigned Bs[2][16 * BSTR];

    const int z = blockIdx.z;
    const float* A    = z == 0 ? A0  : z == 1 ? A1  : A2;
    const float* W    = z == 0 ? W0  : z == 1 ? W1  : W2;
    const float* bias = z == 0 ? bb0 : z == 1 ? bb1 : bb2;
    float*       C    = z == 0 ? C0  : z == 1 ? C1  : C2;

    const int tid  = threadIdx.x;
    const int warp = tid >> 5, lane = tid & 31;
    const int g = lane >> 2, tg = lane & 3;
    const int wm = (warp >> 2) * 64, wn = (warp & 3) * 32;

    // global-load mapping
    const int ar = tid >> 1, ac = (tid & 1) * 8;       // A: 128 rows x 16 k
    const int br = tid >> 4, bc = (tid & 15) * 8;      // W: 16 k x 128 n
    const float* Ag = A + (size_t)(blockIdx.y * 128 + ar) * DMODEL;
    const float* Wg = W + (size_t)br * DMODEL + blockIdx.x * 128 + bc;

    // ldmatrix lane offsets for A-frag x4 tiles
    const int a_row = (lane & 7) + ((lane >> 3) & 1) * 8;
    const int a_col = (lane >> 4) * 4;

    const unsigned asb = (unsigned)__cvta_generic_to_shared(&As[0][0]);
    const unsigned bufstep = 128 * ASTR * 4;

    float acc[4][4][4];
    #pragma unroll
    for (int mi = 0; mi < 4; mi++)
        #pragma unroll
        for (int ni = 0; ni < 4; ni++)
            #pragma unroll
            for (int r = 0; r < 4; r++) acc[mi][ni][r] = 0.f;

    float4 ra0, ra1, rb0, rb1;

    // prologue: k0 = 0
    ra0 = *(const float4*)(Ag + ac);
    ra1 = *(const float4*)(Ag + ac + 4);
    rb0 = *(const float4*)(Wg);
    rb1 = *(const float4*)(Wg + 4);
    {
        uint4 u;
        unsigned* pa = &As[0][ar * ASTR + ac];
        u.x = f2tf(ra0.x); u.y = f2tf(ra0.y); u.z = f2tf(ra0.z); u.w = f2tf(ra0.w);
        *(uint4*)pa = u;
        u.x = f2tf(ra1.x); u.y = f2tf(ra1.y); u.z = f2tf(ra1.z); u.w = f2tf(ra1.w);
        *(uint4*)(pa + 4) = u;
        unsigned* pb = &Bs[0][br * BSTR + bc];
        u.x = f2tf(rb0.x); u.y = f2tf(rb0.y); u.z = f2tf(rb0.z); u.w = f2tf(rb0.w);
        *(uint4*)pb = u;
        u.x = f2tf(rb1.x); u.y = f2tf(rb1.y); u.z = f2tf(rb1.z); u.w = f2tf(rb1.w);
        *(uint4*)(pb + 4) = u;
    }
    __syncthreads();

    int buf = 0;
    for (int k0 = 16; k0 <= DMODEL; k0 += 16) {
        if (k0 < DMODEL) {      // prefetch next tile into registers
            ra0 = *(const float4*)(Ag + k0 + ac);
            ra1 = *(const float4*)(Ag + k0 + ac + 4);
            rb0 = *(const float4*)(Wg + (size_t)k0 * DMODEL);
            rb1 = *(const float4*)(Wg + (size_t)k0 * DMODEL + 4);
        }
        // ---- compute current buffer ----
        #pragma unroll
        for (int ks = 0; ks < 2; ++ks) {
            const int kk = ks * 8;
            unsigned a[4][4], bfr[4][2];
            #pragma unroll
            for (int mi = 0; mi < 4; ++mi)
                ldsm4(a[mi][0], a[mi][1], a[mi][2], a[mi][3],
                      asb + buf * bufstep +
                      ((wm + mi * 16 + a_row) * ASTR + kk + a_col) * 4);
            #pragma unroll
            for (int ni = 0; ni < 4; ++ni) {
                bfr[ni][0] = Bs[buf][(kk + tg    ) * BSTR + wn + ni * 8 + g];
                bfr[ni][1] = Bs[buf][(kk + tg + 4) * BSTR + wn + ni * 8 + g];
            }
            #pragma unroll
            for (int mi = 0; mi < 4; ++mi)
                #pragma unroll
                for (int ni = 0; ni < 4; ++ni)
                    mma8(acc[mi][ni], a[mi], bfr[ni]);
        }
        if (k0 < DMODEL) {      // stage next tile into other buffer
            uint4 u;
            unsigned* pa = &As[buf ^ 1][ar * ASTR + ac];
            u.x = f2tf(ra0.x); u.y = f2tf(ra0.y); u.z = f2tf(ra0.z); u.w = f2tf(ra0.w);
            *(uint4*)pa = u;
            u.x = f2tf(ra1.x); u.y = f2tf(ra1.y); u.z = f2tf(ra1.z); u.w = f2tf(ra1.w);
            *(uint4*)(pa + 4) = u;
            unsigned* pb = &Bs[buf ^ 1][br * BSTR + bc];
            u.x = f2tf(rb0.x); u.y = f2tf(rb0.y); u.z = f2tf(rb0.z); u.w = f2tf(rb0.w);
            *(uint4*)pb = u;
            u.x = f2tf(rb1.x); u.y = f2tf(rb1.y); u.z = f2tf(rb1.z); u.w = f2tf(rb1.w);
            *(uint4*)(pb + 4) = u;
            __syncthreads();
            buf ^= 1;
        }
    }

    // epilogue: bias + store
    #pragma unroll
    for (int mi = 0; mi < 4; ++mi) {
        #pragma unroll
        for (int ni = 0; ni < 4; ++ni) {
            int row = blockIdx.y * 128 + wm + mi * 16 + g;
            int col = blockIdx.x * 128 + wn + ni * 8 + 2 * tg;
            float b0 = bias[col], b1 = bias[col + 1];
            *(float2*)(C + (size_t)row * DMODEL + col) =
                make_float2(acc[mi][ni][0] + b0, acc[mi][ni][1] + b1);
            *(float2*)(C + (size_t)(row + 8) * DMODEL + col) =
                make_float2(acc[mi][ni][2] + b0, acc[mi][ni][3] + b1);
        }
    }
}

// ============================================================================
// Fused flash attention, tf32 tensor cores + ldmatrix fragment loads.
// 128 q-rows/block, 8 warps x 16 rows, kv tiles of 64.
// sQ/sK/sP stride 68 (LDSM segs 17r mod 8 = r distinct); sV stride 72
// (scalar b-frag banks 8tg+8ni+g distinct).
// ============================================================================
#define BQ   128
#define BKV  64
#define QSTR 68
#define KSTR 68
#define VSTR 72
#define PSTR 68
#define OFF_K  (BQ * QSTR)
#define OFF_V  (OFF_K + BKV * KSTR)
#define OFF_P  (OFF_V + BKV * VSTR)
#define ATTN_SMEM ((OFF_P + BQ * PSTR) * sizeof(unsigned))

__global__ __launch_bounds__(256, 2)
void attn_tc_kernel()
{
    extern __shared__ unsigned sm[];
    unsigned* sQ = sm;
    unsigned* sK = sm + OFF_K;
    unsigned* sV = sm + OFF_V;
    unsigned* sP = sm + OFF_P;

    const int tid  = threadIdx.x;
    const int warp = tid >> 5, lane = tid & 31;
    const int g = lane >> 2, tg = lane & 3;
    const int wr0 = warp * 16;
    const int b = blockIdx.y >> 4;
    const int h = blockIdx.y & 15;
    const size_t qrow0 = (size_t)b * SEQ + (size_t)blockIdx.x * BQ;

    const float* Qg = g_Qp + qrow0 * DMODEL + h * HDIM;
    const float* Kg = g_Kp + (size_t)b * SEQ * DMODEL + h * HDIM;
    const float* Vg = g_Vp + (size_t)b * SEQ * DMODEL + h * HDIM;

    // ldmatrix lane offsets
    const int a_row = (lane & 7) + ((lane >> 3) & 1) * 8;  // a-frag tiles
    const int a_col = (lane >> 4) * 4;
    const int b_row = (lane & 7) + ((lane >> 4) & 1) * 8;  // K b-frag tiles (2 ni)
    const int b_col = ((lane >> 3) & 1) * 4;

    const unsigned sQb = (unsigned)__cvta_generic_to_shared(sQ);
    const unsigned sKb = (unsigned)__cvta_generic_to_shared(sK);
    const unsigned sPb = (unsigned)__cvta_generic_to_shared(sP);

    // ---- load Q tile once (scale 1/8 folded in, tf32) ----
    #pragma unroll
    for (int it = 0; it < 8; ++it) {
        int idx = tid + it * 256;
        int r = idx >> 4, c = (idx & 15) * 4;
        float4 v = *(const float4*)(Qg + (size_t)r * DMODEL + c);
        unsigned* d = &sQ[r * QSTR + c];
        uint4 u;
        u.x = f2tf(v.x * 0.125f); u.y = f2tf(v.y * 0.125f);
        u.z = f2tf(v.z * 0.125f); u.w = f2tf(v.w * 0.125f);
        *(uint4*)d = u;
    }

    float o[8][4];
    #pragma unroll
    for (int ni = 0; ni < 8; ni++)
        #pragma unroll
        for (int r = 0; r < 4; r++) o[ni][r] = 0.f;
    float m0 = -CUDART_INF_F, m1 = -CUDART_INF_F, l0 = 0.f, l1 = 0.f;

    for (int kb = 0; kb < SEQ; kb += BKV) {
        __syncthreads();   // prior PV reads of sK/sV done in all warps
        // ---- load K,V tiles (64x64 each), tf32 ----
        #pragma unroll
        for (int it = 0; it < 4; ++it) {
            int idx = tid + it * 256;
            int r = idx >> 4, c = (idx & 15) * 4;
            float4 kv = *(const float4*)(Kg + (size_t)(kb + r) * DMODEL + c);
            uint4 u;
            u.x = f2tf(kv.x); u.y = f2tf(kv.y); u.z = f2tf(kv.z); u.w = f2tf(kv.w);
            *(uint4*)(&sK[r * KSTR + c]) = u;
            float4 vv = *(const float4*)(Vg + (size_t)(kb + r) * DMODEL + c);
            u.x = f2tf(vv.x); u.y = f2tf(vv.y); u.z = f2tf(vv.z); u.w = f2tf(vv.w);
            *(uint4*)(&sV[r * VSTR + c]) = u;
        }
        __syncthreads();

        // ---- S = Q @ K^T : warp computes 16 x 64 ----
        float s[8][4];
        #pragma unroll
        for (int ni = 0; ni < 8; ni++)
            #pragma unroll
            for (int r = 0; r < 4; r++) s[ni][r] = 0.f;

        #pragma unroll
        for (int ks = 0; ks < 8; ++ks) {
            const int kk = ks * 8;
            unsigned a[4];
            ldsm4(a[0], a[1], a[2], a[3],
                  sQb + ((wr0 + a_row) * QSTR + kk + a_col) * 4);
            #pragma unroll
            for (int np = 0; np < 4; ++np) {
                unsigned b4[4];
                ldsm4(b4[0], b4[1], b4[2], b4[3],
                      sKb + ((np * 16 + b_row) * KSTR + kk + b_col) * 4);
                mma8(s[2 * np    ], a, b4);
                mma8(s[2 * np + 1], a, b4 + 2);
            }
        }

        // ---- online softmax (rows wr0+g and wr0+g+8; reduce over quad) ----
        float mx0 = -CUDART_INF_F, mx1 = -CUDART_INF_F;
        #pragma unroll
        for (int ni = 0; ni < 8; ++ni) {
            mx0 = fmaxf(mx0, fmaxf(s[ni][0], s[ni][1]));
            mx1 = fmaxf(mx1, fmaxf(s[ni][2], s[ni][3]));
        }
        mx0 = fmaxf(mx0, __shfl_xor_sync(0xffffffffu, mx0, 1));
        mx0 = fmaxf(mx0, __shfl_xor_sync(0xffffffffu, mx0, 2));
        mx1 = fmaxf(mx1, __shfl_xor_sync(0xffffffffu, mx1, 1));
        mx1 = fmaxf(mx1, __shfl_xor_sync(0xffffffffu, mx1, 2));

        float mn0 = fmaxf(m0, mx0), mn1 = fmaxf(m1, mx1);
        float corr0 = __expf(m0 - mn0), corr1 = __expf(m1 - mn1);
        m0 = mn0; m1 = mn1;

        float sum0 = 0.f, sum1 = 0.f;
        #pragma unroll
        for (int ni = 0; ni < 8; ++ni) {
            float p0 = __expf(s[ni][0] - mn0);
            float p1 = __expf(s[ni][1] - mn0);
            float p2 = __expf(s[ni][2] - mn1);
            float p3 = __expf(s[ni][3] - mn1);
            sum0 += p0 + p1; sum1 += p2 + p3;
            int col = ni * 8 + 2 * tg;
            sP[(wr0 + g    ) * PSTR + col    ] = f2tf(p0);
            sP[(wr0 + g    ) * PSTR + col + 1] = f2tf(p1);
            sP[(wr0 + g + 8) * PSTR + col    ] = f2tf(p2);
            sP[(wr0 + g + 8) * PSTR + col + 1] = f2tf(p3);
        }
        sum0 += __shfl_xor_sync(0xffffffffu, sum0, 1);
        sum0 += __shfl_xor_sync(0xffffffffu, sum0, 2);
        sum1 += __shfl_xor_sync(0xffffffffu, sum1, 1);
        sum1 += __shfl_xor_sync(0xffffffffu, sum1, 2);
        l0 = l0 * corr0 + sum0;
        l1 = l1 * corr1 + sum1;
        #pragma unroll
        for (int ni = 0; ni < 8; ++ni) {
            o[ni][0] *= corr0; o[ni][1] *= corr0;
            o[ni][2] *= corr1; o[ni][3] *= corr1;
        }
        __syncwarp();   // sP rows are warp-private

        // ---- O += P @ V ----
        #pragma unroll
        for (int ks = 0; ks < 8; ++ks) {
            const int kk = ks * 8;
            unsigned a[4];
            ldsm4(a[0], a[1], a[2], a[3],
                  sPb + ((wr0 + a_row) * PSTR + kk + a_col) * 4);
            #pragma unroll
            for (int ni = 0; ni < 8; ++ni) {
                unsigned bfr[2];
                bfr[0] = sV[(kk + tg    ) * VSTR + ni * 8 + g];
                bfr[1] = sV[(kk + tg + 4) * VSTR + ni * 8 + g];
                mma8(o[ni], a, bfr);
            }
        }
    }

    // ---- normalize + write Z in [B*S, H*d] layout ----
    float inv0 = 1.f / l0, inv1 = 1.f / l1;
    #pragma unroll
    for (int ni = 0; ni < 8; ++ni) {
        int col = h * HDIM + ni * 8 + 2 * tg;
        size_t r0 = qrow0 + wr0 + g;
        *(float2*)(g_Z + r0 * DMODEL + col) =
            make_float2(o[ni][0] * inv0, o[ni][1] * inv0);
        *(float2*)(g_Z + (r0 + 8) * DMODEL + col) =
            make_float2(o[ni][2] * inv1, o[ni][3] * inv1);
    }
}

// ============================================================================
// Launch: merged QKV projections -> attention -> output projection.
// ============================================================================
extern "C" void kernel_launch(void* const* d_in, const int* in_sizes, int n_in,
                              void* d_out, int out_size)
{
    const float* query = (const float*)d_in[0];
    const float* key   = (const float*)d_in[1];
    const float* value = (const float*)d_in[2];
    const float* Wq    = (const float*)d_in[3];
    const float* bq    = (const float*)d_in[4];
    const float* Wk    = (const float*)d_in[5];
    const float* bk    = (const float*)d_in[6];
    const float* Wv    = (const float*)d_in[7];
    const float* bv    = (const float*)d_in[8];
    const float* Wo    = (const float*)d_in[9];
    const float* bo    = (const float*)d_in[10];

    float *Qp, *Kp, *Vp, *Zp;
    cudaGetSymbolAddress((void**)&Qp, g_Qp);
    cudaGetSymbolAddress((void**)&Kp, g_Kp);
    cudaGetSymbolAddress((void**)&Vp, g_Vp);
    cudaGetSymbolAddress((void**)&Zp, g_Z);

    dim3 gqkv(DMODEL / 128, ROWS / 128, 3);
    gemm3_tf32<<<gqkv, 256>>>(query, key, value, Wq, Wk, Wv, bq, bk, bv,
                              Qp, Kp, Vp);

    cudaFuncSetAttribute(attn_tc_kernel, cudaFuncAttributeMaxDynamicSharedMemorySize,
                         (int)ATTN_SMEM);
    attn_tc_kernel<<<dim3(SEQ / BQ, BATCH * NHEADS), 256, ATTN_SMEM>>>();

    dim3 go(DMODEL / 128, ROWS / 128, 1);
    gemm3_tf32<<<go, 256>>>(Zp, Zp, Zp, Wo, Wo, Wo, bo, bo, bo,
                            (float*)d_out, (float*)d_out, (float*)d_out);
}